// round 10
// baseline (speedup 1.0000x reference)
#include <cuda_runtime.h>
#include <cuda_bf16.h>
#include <cstdint>

#define N_NODES 50000
#define N_EDGES 800000
#define D_IN    256
#define H_DIM   96
#define BN_EPS  1e-5f

#define BM 128
#define N_BLK 391          // ceil(50000/128)
#define PSTRIDE 400
#define KC 32              // k-chunk (fp32 elems)
#define PA 40              // smem row pitch in bf16 elems (80B, conflict-free)

// ---------------- device scratch ----------------
__device__ __align__(16) float g_h0[N_NODES * H_DIM];
__device__ __align__(16) float g_z [N_NODES * H_DIM];
__device__ __align__(16) float g_h [N_NODES * H_DIM];
__device__ float g_psum [H_DIM * PSTRIDE];
__device__ float g_psq  [H_DIM * PSTRIDE];
__device__ float g_scale[H_DIM];
__device__ float g_shift[H_DIM];
__device__ int   g_is64;
__device__ int   g_done = 0;
// CSR scratch
__device__ int   g_deg [N_NODES];
__device__ int   g_fill[N_NODES];
__device__ int   g_rs  [N_NODES + 1];
__device__ int   g_esrc[N_EDGES];

// ---------------- smem layout (bytes into dynamic smem) ----------------
#define OFF_SCALE 0
#define OFF_SHIFT 384
#define OFF_A     768
#define A_HL      10240            // 128 rows * 40 elems * 2B
#define OFF_B     (OFF_A + 4 * A_HL)
#define B_HL      7680             // 96 * 40 * 2
#define SMEM_DYN  (OFF_B + 4 * B_HL)        // 72448

#define MMA(d, a, b) \
    asm volatile("mma.sync.aligned.m16n8k16.row.col.f32.bf16.bf16.f32 " \
                 "{%0,%1,%2,%3},{%4,%5,%6,%7},{%8,%9},{%0,%1,%2,%3};" \
                 : "+f"(d[0]), "+f"(d[1]), "+f"(d[2]), "+f"(d[3]) \
                 : "r"(a[0]), "r"(a[1]), "r"(a[2]), "r"(a[3]), "r"(b[0]), "r"(b[1]))

__device__ __forceinline__ uint32_t pack_hi(float v0, float v1, float& r0, float& r1) {
    __nv_bfloat162 hp = __floats2bfloat162_rn(v0, v1);
    r0 = __bfloat162float(__low2bfloat16(hp));
    r1 = __bfloat162float(__high2bfloat16(hp));
    return *reinterpret_cast<uint32_t*>(&hp);
}

__device__ __forceinline__ int edge_idx(const void* ei, size_t off) {
    return g_is64 ? (int)((const long long*)ei)[off] : ((const int*)ei)[off];
}

// =====================================================================
// Split-bf16 tensor-core GEMM via mma.sync:
//   out[N,96] = A[N,KD] @ W[96,KD]^T + bias
// MODE 0: A = x -> g_h0; also: dtype probe, zero CSR/stat scratch
// MODE 1: A = g_z -> g_h + BN partials; LAST block reduces -> scale/shift
// MODE 2: A = g_h (BN+ReLU on load) -> out
// =====================================================================
template<int KD, int MODE>
__global__ __launch_bounds__(256) void k_tgemm(const float* __restrict__ A_,
                                               const float* __restrict__ W,
                                               const float* __restrict__ bias,
                                               float* __restrict__ out,
                                               const int* __restrict__ ei32,
                                               const float* __restrict__ gamma,
                                               const float* __restrict__ beta) {
    constexpr int NC = KD / KC;
    extern __shared__ char smem[];

    const int tid    = threadIdx.x;
    const int lane   = tid & 31;
    const int wid    = tid >> 5;
    const int warp_m = wid >> 1;
    const int warp_n = wid & 1;
    const int g      = lane >> 2;
    const int t4     = lane & 3;
    const int row0   = blockIdx.x * BM;

    float* s_scale = (float*)(smem + OFF_SCALE);
    float* s_shift = (float*)(smem + OFF_SHIFT);
    __shared__ int s_last;

    if (MODE == 0) {
        // zero CSR + stat scratch (grid covers >= N_NODES threads)
        const int gtid = blockIdx.x * 256 + tid;
        if (gtid < N_NODES) { g_deg[gtid] = 0; g_fill[gtid] = 0; }
        if (blockIdx.x == 0 && tid == 0) {
            int nz = 0;
#pragma unroll
            for (int i = 0; i < 64; i++) nz |= ei32[2 * i + 1];
            g_is64 = (nz == 0) ? 1 : 0;
            g_done = 0;
        }
    }
    if (MODE == 2 && tid < H_DIM) {
        s_scale[tid] = g_scale[tid];
        s_shift[tid] = g_shift[tid];
    }
    __syncthreads();

    const float* Ap = (MODE == 0) ? A_ : (MODE == 1 ? g_z : g_h);

    auto pAh = [&](int b) { return (char*)smem + OFF_A + b * 2 * A_HL; };
    auto pAl = [&](int b) { return (char*)smem + OFF_A + b * 2 * A_HL + A_HL; };
    auto pBh = [&](int b) { return (char*)smem + OFF_B + b * 2 * B_HL; };
    auto pBl = [&](int b) { return (char*)smem + OFF_B + b * 2 * B_HL + B_HL; };

    const int arow  = tid >> 1;
    const int ahalf = (tid & 1) * 16;
    float ra[16];
    float rb[12];

    auto ldgA = [&](int c) {
        const int gr = row0 + arow;
        const int kb = c * KC + ahalf;
        if (gr < N_NODES) {
#pragma unroll
            for (int q = 0; q < 4; q++) {
                float4 f = *reinterpret_cast<const float4*>(&Ap[(size_t)gr * KD + kb + q * 4]);
                ra[q*4+0] = f.x; ra[q*4+1] = f.y; ra[q*4+2] = f.z; ra[q*4+3] = f.w;
            }
            if (MODE == 2) {
#pragma unroll
                for (int q = 0; q < 16; q++)
                    ra[q] = fmaxf(ra[q] * s_scale[kb + q] + s_shift[kb + q], 0.f);
            }
        } else {
#pragma unroll
            for (int q = 0; q < 16; q++) ra[q] = 0.f;
        }
    };
    auto stsA = [&](int b) {
        char* ah = pAh(b);
        char* al = pAl(b);
#pragma unroll
        for (int j = 0; j < 8; j++) {
            float v0 = ra[2*j], v1 = ra[2*j+1], h0, h1;
            uint32_t hp = pack_hi(v0, v1, h0, h1);
            __nv_bfloat162 lo2 = __floats2bfloat162_rn(v0 - h0, v1 - h1);
            int boff = (arow * PA + ahalf + 2*j) * 2;
            *reinterpret_cast<uint32_t*>(ah + boff) = hp;
            *reinterpret_cast<uint32_t*>(al + boff) = *reinterpret_cast<uint32_t*>(&lo2);
        }
    };
    auto ldgB = [&](int c) {
#pragma unroll
        for (int q = 0; q < 3; q++) {
            int f4 = tid + q * 256;
            int rw = f4 >> 3;
            int kq = (f4 & 7) * 4;
            float4 f = *reinterpret_cast<const float4*>(&W[(size_t)rw * KD + c * KC + kq]);
            rb[q*4+0] = f.x; rb[q*4+1] = f.y; rb[q*4+2] = f.z; rb[q*4+3] = f.w;
        }
    };
    auto stsB = [&](int b) {
        char* bh = pBh(b);
        char* bl = pBl(b);
#pragma unroll
        for (int q = 0; q < 3; q++) {
            int f4 = tid + q * 256;
            int rw = f4 >> 3;
            int kq = (f4 & 7) * 4;
#pragma unroll
            for (int j = 0; j < 2; j++) {
                float v0 = rb[q*4 + 2*j], v1 = rb[q*4 + 2*j + 1], h0, h1;
                uint32_t hp = pack_hi(v0, v1, h0, h1);
                __nv_bfloat162 lo2 = __floats2bfloat162_rn(v0 - h0, v1 - h1);
                int boff = (rw * PA + kq + 2*j) * 2;
                *reinterpret_cast<uint32_t*>(bh + boff) = hp;
                *reinterpret_cast<uint32_t*>(bl + boff) = *reinterpret_cast<uint32_t*>(&lo2);
            }
        }
    };

    float acc[2][6][4];
#pragma unroll
    for (int mt = 0; mt < 2; mt++)
#pragma unroll
        for (int nt = 0; nt < 6; nt++)
#pragma unroll
            for (int q = 0; q < 4; q++) acc[mt][nt][q] = 0.f;

    auto compute = [&](int b) {
        const char* Ah = pAh(b);
        const char* Al = pAl(b);
        const char* Bh = pBh(b);
        const char* Bl = pBl(b);
#pragma unroll
        for (int kk = 0; kk < KC; kk += 16) {
            uint32_t ah[2][4], al[2][4], bh[6][2], bl[6][2];
#pragma unroll
            for (int mt = 0; mt < 2; mt++) {
                int r0 = warp_m * 32 + mt * 16 + g;
                int e0 = (r0 * PA + kk + t4 * 2) * 2;
                int e1 = ((r0 + 8) * PA + kk + t4 * 2) * 2;
                ah[mt][0] = *reinterpret_cast<const uint32_t*>(Ah + e0);
                ah[mt][1] = *reinterpret_cast<const uint32_t*>(Ah + e1);
                ah[mt][2] = *reinterpret_cast<const uint32_t*>(Ah + e0 + 16);
                ah[mt][3] = *reinterpret_cast<const uint32_t*>(Ah + e1 + 16);
                al[mt][0] = *reinterpret_cast<const uint32_t*>(Al + e0);
                al[mt][1] = *reinterpret_cast<const uint32_t*>(Al + e1);
                al[mt][2] = *reinterpret_cast<const uint32_t*>(Al + e0 + 16);
                al[mt][3] = *reinterpret_cast<const uint32_t*>(Al + e1 + 16);
            }
#pragma unroll
            for (int nt = 0; nt < 6; nt++) {
                int n = warp_n * 48 + nt * 8 + g;
                int e = (n * PA + kk + t4 * 2) * 2;
                bh[nt][0] = *reinterpret_cast<const uint32_t*>(Bh + e);
                bh[nt][1] = *reinterpret_cast<const uint32_t*>(Bh + e + 16);
                bl[nt][0] = *reinterpret_cast<const uint32_t*>(Bl + e);
                bl[nt][1] = *reinterpret_cast<const uint32_t*>(Bl + e + 16);
            }
#pragma unroll
            for (int mt = 0; mt < 2; mt++)
#pragma unroll
                for (int nt = 0; nt < 6; nt++) {
                    MMA(acc[mt][nt], ah[mt], bh[nt]);
                    MMA(acc[mt][nt], al[mt], bh[nt]);
                    MMA(acc[mt][nt], ah[mt], bl[nt]);
                }
        }
    };

    ldgA(0); ldgB(0);
    stsA(0); stsB(0);
    __syncthreads();
    for (int c = 0; c < NC; c++) {
        const bool pf = (c + 1 < NC);
        if (pf) { ldgA(c + 1); ldgB(c + 1); }
        compute(c & 1);
        if (pf) {
            stsA((c + 1) & 1); stsB((c + 1) & 1);
            __syncthreads();
        }
    }
    __syncthreads();

    // ---- epilogue: acc -> smem staging (pitch 100 floats) ----
    float* sD = (float*)(smem + OFF_A);
#pragma unroll
    for (int mt = 0; mt < 2; mt++) {
        int r0 = warp_m * 32 + mt * 16 + g;
#pragma unroll
        for (int nt = 0; nt < 6; nt++) {
            int cb = warp_n * 48 + nt * 8 + t4 * 2;
            sD[r0 * 100 + cb]       = acc[mt][nt][0];
            sD[r0 * 100 + cb + 1]   = acc[mt][nt][1];
            sD[(r0+8) * 100 + cb]   = acc[mt][nt][2];
            sD[(r0+8) * 100 + cb+1] = acc[mt][nt][3];
        }
    }
    __syncthreads();

    const int rmax = min(BM, N_NODES - row0);

    if (MODE == 1) {
        if (tid < H_DIM) {
            const float b = bias[tid];
            float s = 0.f, q = 0.f;
            for (int r = 0; r < rmax; r++) {
                float v = sD[r * 100 + tid] + b;
                s += v; q += v * v;
            }
            g_psum[tid * PSTRIDE + blockIdx.x] = s;
            g_psq [tid * PSTRIDE + blockIdx.x] = q;
        }
    }

    for (int idx = tid; idx < rmax * 24; idx += 256) {
        int r = idx / 24, c4 = idx % 24;
        float4 v = *reinterpret_cast<const float4*>(&sD[r * 100 + c4 * 4]);
        float4 b = *reinterpret_cast<const float4*>(&bias[c4 * 4]);
        v.x += b.x; v.y += b.y; v.z += b.z; v.w += b.w;
        size_t o = (size_t)(row0 + r) * H_DIM + c4 * 4;
        if (MODE == 0) {
            *reinterpret_cast<float4*>(&g_h0[o]) = v;
        } else if (MODE == 1) {
            *reinterpret_cast<float4*>(&g_h[o]) = v;
        } else {
            *reinterpret_cast<float4*>(&out[o]) = v;
        }
    }

    if (MODE == 1) {
        // last finishing block reduces partials -> scale/shift (replaces k_finalize)
        __threadfence();
        __syncthreads();
        if (tid == 0) s_last = (atomicAdd(&g_done, 1) == N_BLK - 1) ? 1 : 0;
        __syncthreads();
        if (s_last) {
            if (tid < H_DIM) {
                float s = 0.f, q = 0.f;
                for (int b = 0; b < N_BLK; b++) {
                    s += g_psum[tid * PSTRIDE + b];
                    q += g_psq [tid * PSTRIDE + b];
                }
                const float inv_n = 1.0f / (float)N_NODES;
                float mu  = s * inv_n;
                float var = q * inv_n - mu * mu;
                float sc  = gamma[tid] * rsqrtf(var + BN_EPS);
                g_scale[tid] = sc;
                g_shift[tid] = beta[tid] - mu * sc;
            }
            if (tid == 0) g_done = 0;
        }
    }
}

// =====================================================================
// CSR build: histogram -> scan -> permute
// =====================================================================
__global__ __launch_bounds__(256) void k_hist(const void* __restrict__ ei) {
    int e = blockIdx.x * 256 + threadIdx.x;
    if (e >= N_EDGES) return;
    int dst = edge_idx(ei, (size_t)N_EDGES + e);
    if ((unsigned)dst < N_NODES) atomicAdd(&g_deg[dst], 1);
}

__global__ __launch_bounds__(1024) void k_scan() {
    __shared__ int s[1024];
    const int t = threadIdx.x;
    const int PER = 49;                       // 1024*49 >= 50000
    const int base = t * PER;
    int sum = 0;
    for (int i = 0; i < PER; i++) {
        int idx = base + i;
        sum += (idx < N_NODES) ? g_deg[idx] : 0;
    }
    s[t] = sum;
    __syncthreads();
    for (int off = 1; off < 1024; off <<= 1) {
        int v = (t >= off) ? s[t - off] : 0;
        __syncthreads();
        s[t] += v;
        __syncthreads();
    }
    int run = s[t] - sum;                     // exclusive prefix
    for (int i = 0; i < PER; i++) {
        int idx = base + i;
        if (idx < N_NODES) {
            g_rs[idx] = run;
            run += g_deg[idx];
        }
    }
    if (t == 1023) g_rs[N_NODES] = s[1023];
}

__global__ __launch_bounds__(256) void k_permute(const void* __restrict__ ei) {
    int e = blockIdx.x * 256 + threadIdx.x;
    if (e >= N_EDGES) return;
    int src = edge_idx(ei, (size_t)e);
    int dst = edge_idx(ei, (size_t)N_EDGES + e);
    if ((unsigned)src >= N_NODES || (unsigned)dst >= N_NODES) return;
    int pos = g_rs[dst] + atomicAdd(&g_fill[dst], 1);
    g_esrc[pos] = src;
}

// =====================================================================
// Pull aggregation: warp per node, z[n] = h0[n] + sum_{e in CSR(n)} h0[src]
// lane handles columns {lane, lane+32, lane+64}; edge loop unrolled x4.
// =====================================================================
__global__ __launch_bounds__(256) void k_aggregate() {
    const int warp = threadIdx.x >> 5;
    const int lane = threadIdx.x & 31;
    const int n    = blockIdx.x * 8 + warp;
    if (n >= N_NODES) return;

    const int rs = g_rs[n];
    const int re = g_rs[n + 1];
    float a0 = 0.f, a1 = 0.f, a2 = 0.f;

    int e = rs;
    for (; e + 4 <= re; e += 4) {
        const int s0 = g_esrc[e], s1 = g_esrc[e+1], s2 = g_esrc[e+2], s3 = g_esrc[e+3];
        const float* r0 = &g_h0[(size_t)s0 * H_DIM + lane];
        const float* r1 = &g_h0[(size_t)s1 * H_DIM + lane];
        const float* r2 = &g_h0[(size_t)s2 * H_DIM + lane];
        const float* r3 = &g_h0[(size_t)s3 * H_DIM + lane];
        float v00 = r0[0], v01 = r0[32], v02 = r0[64];
        float v10 = r1[0], v11 = r1[32], v12 = r1[64];
        float v20 = r2[0], v21 = r2[32], v22 = r2[64];
        float v30 = r3[0], v31 = r3[32], v32 = r3[64];
        a0 += v00 + v10 + v20 + v30;
        a1 += v01 + v11 + v21 + v31;
        a2 += v02 + v12 + v22 + v32;
    }
    for (; e < re; e++) {
        const int s0 = g_esrc[e];
        const float* r0 = &g_h0[(size_t)s0 * H_DIM + lane];
        a0 += r0[0]; a1 += r0[32]; a2 += r0[64];
    }

    const float* hs = &g_h0[(size_t)n * H_DIM + lane];
    float*       zs = &g_z [(size_t)n * H_DIM + lane];
    zs[0]  = a0 + hs[0];
    zs[32] = a1 + hs[32];
    zs[64] = a2 + hs[64];
}

// =====================================================================
// launch
// =====================================================================
extern "C" void kernel_launch(void* const* d_in, const int* in_sizes, int n_in,
                              void* d_out, int out_size) {
    const float* x     = (const float*)d_in[0];
    const void*  ei    = d_in[1];
    const float* W0    = (const float*)d_in[2];
    const float* b0    = (const float*)d_in[3];
    const float* W1    = (const float*)d_in[4];
    const float* b1    = (const float*)d_in[5];
    const float* gamma = (const float*)d_in[6];
    const float* beta  = (const float*)d_in[7];
    const float* W2    = (const float*)d_in[8];
    const float* b2    = (const float*)d_in[9];
    float*       out   = (float*)d_out;

    static bool attr_done = false;
    if (!attr_done) {
        cudaFuncSetAttribute(k_tgemm<D_IN, 0>, cudaFuncAttributeMaxDynamicSharedMemorySize, SMEM_DYN);
        cudaFuncSetAttribute(k_tgemm<H_DIM, 1>, cudaFuncAttributeMaxDynamicSharedMemorySize, SMEM_DYN);
        cudaFuncSetAttribute(k_tgemm<H_DIM, 2>, cudaFuncAttributeMaxDynamicSharedMemorySize, SMEM_DYN);
        attr_done = true;
    }

    const int eblocks = (N_EDGES + 255) / 256;          // 3125
    const int ablocks = (N_NODES + 7) / 8;              // 6250

    k_tgemm<D_IN, 0><<<N_BLK, 256, SMEM_DYN>>>(x, W0, b0, nullptr, (const int*)ei, nullptr, nullptr);
    k_hist<<<eblocks, 256>>>(ei);
    k_scan<<<1, 1024>>>();
    k_permute<<<eblocks, 256>>>(ei);
    k_aggregate<<<ablocks, 256>>>();
    k_tgemm<H_DIM, 1><<<N_BLK, 256, SMEM_DYN>>>(nullptr, W1, b1, nullptr, nullptr, gamma, beta);
    k_tgemm<H_DIM, 2><<<N_BLK, 256, SMEM_DYN>>>(nullptr, W2, b2, out, nullptr, nullptr, nullptr);
}

// round 11
// speedup vs baseline: 1.2062x; 1.2062x over previous
#include <cuda_runtime.h>
#include <cuda_bf16.h>
#include <cstdint>

#define N_NODES 50000
#define N_EDGES 800000
#define D_IN    256
#define H_DIM   96
#define BN_EPS  1e-5f

#define BM 128
#define N_BLK 391          // ceil(50000/128)
#define PSTRIDE 400
#define KC 32              // k-chunk (fp32 elems)
#define PA 40              // smem row pitch in bf16 elems (80B, conflict-free)
#define EPB 32             // edges per scatter block

// ---------------- device scratch ----------------
__device__ __align__(16) float g_h0[N_NODES * H_DIM];
__device__ __align__(16) float g_z [N_NODES * H_DIM];
__device__ __align__(16) float g_h [N_NODES * H_DIM];
__device__ float g_psum [H_DIM * PSTRIDE];
__device__ float g_psq  [H_DIM * PSTRIDE];
__device__ float g_scale[H_DIM];
__device__ float g_shift[H_DIM];
__device__ int   g_is64;
__device__ int   g_done = 0;

// ---------------- smem layout (bytes into dynamic smem) ----------------
#define OFF_SCALE 0
#define OFF_SHIFT 384
#define OFF_A     768
#define A_HL      10240            // 128 rows * 40 elems * 2B
#define OFF_B     (OFF_A + 4 * A_HL)
#define B_HL      7680             // 96 * 40 * 2
#define SMEM_DYN  (OFF_B + 4 * B_HL)        // 72448

#define MMA(d, a, b) \
    asm volatile("mma.sync.aligned.m16n8k16.row.col.f32.bf16.bf16.f32 " \
                 "{%0,%1,%2,%3},{%4,%5,%6,%7},{%8,%9},{%0,%1,%2,%3};" \
                 : "+f"(d[0]), "+f"(d[1]), "+f"(d[2]), "+f"(d[3]) \
                 : "r"(a[0]), "r"(a[1]), "r"(a[2]), "r"(a[3]), "r"(b[0]), "r"(b[1]))

__device__ __forceinline__ uint32_t pack_hi(float v0, float v1, float& r0, float& r1) {
    __nv_bfloat162 hp = __floats2bfloat162_rn(v0, v1);
    r0 = __bfloat162float(__low2bfloat16(hp));
    r1 = __bfloat162float(__high2bfloat16(hp));
    return *reinterpret_cast<uint32_t*>(&hp);
}

// =====================================================================
// Split-bf16 tensor-core GEMM via mma.sync:
//   out[N,96] = A[N,KD] @ W[96,KD]^T + bias
// MODE 0: A = x -> g_h0, g_z   (+ edge dtype probe in block 0)
// MODE 1: A = g_z -> g_h + BN partials; LAST block -> scale/shift
// MODE 2: A = g_h (BN+ReLU on load) -> out
// =====================================================================
template<int KD, int MODE>
__global__ __launch_bounds__(256) void k_tgemm(const float* __restrict__ A_,
                                               const float* __restrict__ W,
                                               const float* __restrict__ bias,
                                               float* __restrict__ out,
                                               const int* __restrict__ ei32,
                                               const float* __restrict__ gamma,
                                               const float* __restrict__ beta) {
    constexpr int NC = KD / KC;
    extern __shared__ char smem[];

    const int tid    = threadIdx.x;
    const int lane   = tid & 31;
    const int wid    = tid >> 5;
    const int warp_m = wid >> 1;
    const int warp_n = wid & 1;
    const int g      = lane >> 2;
    const int t4     = lane & 3;
    const int row0   = blockIdx.x * BM;

    float* s_scale = (float*)(smem + OFF_SCALE);
    float* s_shift = (float*)(smem + OFF_SHIFT);
    __shared__ int s_last;

    if (MODE == 0 && blockIdx.x == 0 && tid == 0) {
        int nz = 0;
#pragma unroll
        for (int i = 0; i < 64; i++) nz |= ei32[2 * i + 1];
        g_is64 = (nz == 0) ? 1 : 0;
        g_done = 0;
    }
    if (MODE == 2 && tid < H_DIM) {
        s_scale[tid] = g_scale[tid];
        s_shift[tid] = g_shift[tid];
    }
    __syncthreads();

    const float* Ap = (MODE == 0) ? A_ : (MODE == 1 ? g_z : g_h);

    auto pAh = [&](int b) { return (char*)smem + OFF_A + b * 2 * A_HL; };
    auto pAl = [&](int b) { return (char*)smem + OFF_A + b * 2 * A_HL + A_HL; };
    auto pBh = [&](int b) { return (char*)smem + OFF_B + b * 2 * B_HL; };
    auto pBl = [&](int b) { return (char*)smem + OFF_B + b * 2 * B_HL + B_HL; };

    const int arow  = tid >> 1;
    const int ahalf = (tid & 1) * 16;
    float ra[16];
    float rb[12];

    auto ldgA = [&](int c) {
        const int gr = row0 + arow;
        const int kb = c * KC + ahalf;
        if (gr < N_NODES) {
#pragma unroll
            for (int q = 0; q < 4; q++) {
                float4 f = *reinterpret_cast<const float4*>(&Ap[(size_t)gr * KD + kb + q * 4]);
                ra[q*4+0] = f.x; ra[q*4+1] = f.y; ra[q*4+2] = f.z; ra[q*4+3] = f.w;
            }
            if (MODE == 2) {
#pragma unroll
                for (int q = 0; q < 16; q++)
                    ra[q] = fmaxf(ra[q] * s_scale[kb + q] + s_shift[kb + q], 0.f);
            }
        } else {
#pragma unroll
            for (int q = 0; q < 16; q++) ra[q] = 0.f;
        }
    };
    auto stsA = [&](int b) {
        char* ah = pAh(b);
        char* al = pAl(b);
#pragma unroll
        for (int j = 0; j < 8; j++) {
            float v0 = ra[2*j], v1 = ra[2*j+1], h0, h1;
            uint32_t hp = pack_hi(v0, v1, h0, h1);
            __nv_bfloat162 lo2 = __floats2bfloat162_rn(v0 - h0, v1 - h1);
            int boff = (arow * PA + ahalf + 2*j) * 2;
            *reinterpret_cast<uint32_t*>(ah + boff) = hp;
            *reinterpret_cast<uint32_t*>(al + boff) = *reinterpret_cast<uint32_t*>(&lo2);
        }
    };
    auto ldgB = [&](int c) {
#pragma unroll
        for (int q = 0; q < 3; q++) {
            int f4 = tid + q * 256;
            int rw = f4 >> 3;
            int kq = (f4 & 7) * 4;
            float4 f = *reinterpret_cast<const float4*>(&W[(size_t)rw * KD + c * KC + kq]);
            rb[q*4+0] = f.x; rb[q*4+1] = f.y; rb[q*4+2] = f.z; rb[q*4+3] = f.w;
        }
    };
    auto stsB = [&](int b) {
        char* bh = pBh(b);
        char* bl = pBl(b);
#pragma unroll
        for (int q = 0; q < 3; q++) {
            int f4 = tid + q * 256;
            int rw = f4 >> 3;
            int kq = (f4 & 7) * 4;
#pragma unroll
            for (int j = 0; j < 2; j++) {
                float v0 = rb[q*4 + 2*j], v1 = rb[q*4 + 2*j + 1], h0, h1;
                uint32_t hp = pack_hi(v0, v1, h0, h1);
                __nv_bfloat162 lo2 = __floats2bfloat162_rn(v0 - h0, v1 - h1);
                int boff = (rw * PA + kq + 2*j) * 2;
                *reinterpret_cast<uint32_t*>(bh + boff) = hp;
                *reinterpret_cast<uint32_t*>(bl + boff) = *reinterpret_cast<uint32_t*>(&lo2);
            }
        }
    };

    float acc[2][6][4];
#pragma unroll
    for (int mt = 0; mt < 2; mt++)
#pragma unroll
        for (int nt = 0; nt < 6; nt++)
#pragma unroll
            for (int q = 0; q < 4; q++) acc[mt][nt][q] = 0.f;

    auto compute = [&](int b) {
        const char* Ah = pAh(b);
        const char* Al = pAl(b);
        const char* Bh = pBh(b);
        const char* Bl = pBl(b);
#pragma unroll
        for (int kk = 0; kk < KC; kk += 16) {
            uint32_t ah[2][4], al[2][4], bh[6][2], bl[6][2];
#pragma unroll
            for (int mt = 0; mt < 2; mt++) {
                int r0 = warp_m * 32 + mt * 16 + g;
                int e0 = (r0 * PA + kk + t4 * 2) * 2;
                int e1 = ((r0 + 8) * PA + kk + t4 * 2) * 2;
                ah[mt][0] = *reinterpret_cast<const uint32_t*>(Ah + e0);
                ah[mt][1] = *reinterpret_cast<const uint32_t*>(Ah + e1);
                ah[mt][2] = *reinterpret_cast<const uint32_t*>(Ah + e0 + 16);
                ah[mt][3] = *reinterpret_cast<const uint32_t*>(Ah + e1 + 16);
                al[mt][0] = *reinterpret_cast<const uint32_t*>(Al + e0);
                al[mt][1] = *reinterpret_cast<const uint32_t*>(Al + e1);
                al[mt][2] = *reinterpret_cast<const uint32_t*>(Al + e0 + 16);
                al[mt][3] = *reinterpret_cast<const uint32_t*>(Al + e1 + 16);
            }
#pragma unroll
            for (int nt = 0; nt < 6; nt++) {
                int n = warp_n * 48 + nt * 8 + g;
                int e = (n * PA + kk + t4 * 2) * 2;
                bh[nt][0] = *reinterpret_cast<const uint32_t*>(Bh + e);
                bh[nt][1] = *reinterpret_cast<const uint32_t*>(Bh + e + 16);
                bl[nt][0] = *reinterpret_cast<const uint32_t*>(Bl + e);
                bl[nt][1] = *reinterpret_cast<const uint32_t*>(Bl + e + 16);
            }
#pragma unroll
            for (int mt = 0; mt < 2; mt++)
#pragma unroll
                for (int nt = 0; nt < 6; nt++) {
                    MMA(acc[mt][nt], ah[mt], bh[nt]);
                    MMA(acc[mt][nt], al[mt], bh[nt]);
                    MMA(acc[mt][nt], ah[mt], bl[nt]);
                }
        }
    };

    ldgA(0); ldgB(0);
    stsA(0); stsB(0);
    __syncthreads();
    for (int c = 0; c < NC; c++) {
        const bool pf = (c + 1 < NC);
        if (pf) { ldgA(c + 1); ldgB(c + 1); }
        compute(c & 1);
        if (pf) {
            stsA((c + 1) & 1); stsB((c + 1) & 1);
            __syncthreads();
        }
    }
    __syncthreads();

    // ---- epilogue: acc -> smem staging (pitch 100 floats) ----
    float* sD = (float*)(smem + OFF_A);
#pragma unroll
    for (int mt = 0; mt < 2; mt++) {
        int r0 = warp_m * 32 + mt * 16 + g;
#pragma unroll
        for (int nt = 0; nt < 6; nt++) {
            int cb = warp_n * 48 + nt * 8 + t4 * 2;
            sD[r0 * 100 + cb]       = acc[mt][nt][0];
            sD[r0 * 100 + cb + 1]   = acc[mt][nt][1];
            sD[(r0+8) * 100 + cb]   = acc[mt][nt][2];
            sD[(r0+8) * 100 + cb+1] = acc[mt][nt][3];
        }
    }
    __syncthreads();

    const int rmax = min(BM, N_NODES - row0);

    if (MODE == 1) {
        // BN partials: 192 threads, 2 row-halves per column
        __shared__ float s2sum[2][H_DIM], s2sq[2][H_DIM];
        if (tid < 2 * H_DIM) {
            const int c    = tid % H_DIM;
            const int half = tid / H_DIM;
            const float b  = bias[c];
            const int rlo  = half * 64;
            const int rhi  = min(rmax, rlo + 64);
            float s = 0.f, q = 0.f;
            for (int r = rlo; r < rhi; r++) {
                float v = sD[r * 100 + c] + b;
                s += v; q += v * v;
            }
            s2sum[half][c] = s; s2sq[half][c] = q;
        }
        __syncthreads();
        if (tid < H_DIM) {
            g_psum[tid * PSTRIDE + blockIdx.x] = s2sum[0][tid] + s2sum[1][tid];
            g_psq [tid * PSTRIDE + blockIdx.x] = s2sq [0][tid] + s2sq [1][tid];
        }
    }

    for (int idx = tid; idx < rmax * 24; idx += 256) {
        int r = idx / 24, c4 = idx % 24;
        float4 v = *reinterpret_cast<const float4*>(&sD[r * 100 + c4 * 4]);
        float4 b = *reinterpret_cast<const float4*>(&bias[c4 * 4]);
        v.x += b.x; v.y += b.y; v.z += b.z; v.w += b.w;
        size_t o = (size_t)(row0 + r) * H_DIM + c4 * 4;
        if (MODE == 0) {
            *reinterpret_cast<float4*>(&g_h0[o]) = v;
            *reinterpret_cast<float4*>(&g_z [o]) = v;
        } else if (MODE == 1) {
            *reinterpret_cast<float4*>(&g_h[o]) = v;
        } else {
            *reinterpret_cast<float4*>(&out[o]) = v;
        }
    }

    if (MODE == 1) {
        // last finishing block reduces partials -> scale/shift
        __threadfence();
        __syncthreads();
        if (tid == 0) s_last = (atomicAdd(&g_done, 1) == N_BLK - 1) ? 1 : 0;
        __syncthreads();
        if (s_last) {
            if (tid < H_DIM) {
                float s = 0.f, q = 0.f;
                for (int b = 0; b < N_BLK; b++) {
                    s += g_psum[tid * PSTRIDE + b];
                    q += g_psq [tid * PSTRIDE + b];
                }
                const float inv_n = 1.0f / (float)N_NODES;
                float mu  = s * inv_n;
                float var = q * inv_n - mu * mu;
                float sc  = gamma[tid] * rsqrtf(var + BN_EPS);
                g_scale[tid] = sc;
                g_shift[tid] = beta[tid] - mu * sc;
            }
            if (tid == 0) g_done = 0;
        }
    }
}

// =====================================================================
// Scatter-add  z[dst] += h0[src].  Block = 32 edges; indices staged in
// smem once; each thread: 3 col-groups (float4) of its edge.
// =====================================================================
__global__ __launch_bounds__(256) void k_scatter(const void* __restrict__ ei) {
    __shared__ int s_src[EPB], s_dst[EPB];
    const int tid = threadIdx.x;
    const int e0  = blockIdx.x * EPB;

    if (tid < 2 * EPB) {
        const int which = tid >> 5;          // 0: src, 1: dst
        const int i     = tid & 31;
        const int e     = e0 + i;
        int v = -1;
        if (e < N_EDGES) {
            const size_t off = which ? (size_t)N_EDGES + e : (size_t)e;
            v = g_is64 ? (int)((const long long*)ei)[off]
                       : ((const int*)ei)[off];
        }
        if (which) s_dst[i] = v; else s_src[i] = v;
    }
    __syncthreads();

    const int eL = tid >> 3;                 // 0..31
    const int c8 = tid & 7;                  // 0..7
    if (e0 + eL >= N_EDGES) return;
    const int src = s_src[eL];
    const int dst = s_dst[eL];
    if ((unsigned)src >= N_NODES || (unsigned)dst >= N_NODES) return;

    const float* srow = &g_h0[(size_t)src * H_DIM];
    float*       drow = &g_z [(size_t)dst * H_DIM];
#pragma unroll
    for (int j = 0; j < 3; j++) {
        const int c = (c8 + j * 8) * 4;
        const float4 v = *reinterpret_cast<const float4*>(srow + c);
        asm volatile("red.global.add.v4.f32 [%0], {%1,%2,%3,%4};"
                     :: "l"(drow + c), "f"(v.x), "f"(v.y), "f"(v.z), "f"(v.w)
                     : "memory");
    }
}

// =====================================================================
// launch
// =====================================================================
extern "C" void kernel_launch(void* const* d_in, const int* in_sizes, int n_in,
                              void* d_out, int out_size) {
    const float* x     = (const float*)d_in[0];
    const void*  ei    = d_in[1];
    const float* W0    = (const float*)d_in[2];
    const float* b0    = (const float*)d_in[3];
    const float* W1    = (const float*)d_in[4];
    const float* b1    = (const float*)d_in[5];
    const float* gamma = (const float*)d_in[6];
    const float* beta  = (const float*)d_in[7];
    const float* W2    = (const float*)d_in[8];
    const float* b2    = (const float*)d_in[9];
    float*       out   = (float*)d_out;

    static bool attr_done = false;
    if (!attr_done) {
        cudaFuncSetAttribute(k_tgemm<D_IN, 0>, cudaFuncAttributeMaxDynamicSharedMemorySize, SMEM_DYN);
        cudaFuncSetAttribute(k_tgemm<H_DIM, 1>, cudaFuncAttributeMaxDynamicSharedMemorySize, SMEM_DYN);
        cudaFuncSetAttribute(k_tgemm<H_DIM, 2>, cudaFuncAttributeMaxDynamicSharedMemorySize, SMEM_DYN);
        attr_done = true;
    }

    const int scat_blocks = (N_EDGES + EPB - 1) / EPB;   // 25000

    k_tgemm<D_IN, 0><<<N_BLK, 256, SMEM_DYN>>>(x, W0, b0, nullptr, (const int*)ei, nullptr, nullptr);
    k_scatter<<<scat_blocks, 256>>>(ei);
    k_tgemm<H_DIM, 1><<<N_BLK, 256, SMEM_DYN>>>(nullptr, W1, b1, nullptr, nullptr, gamma, beta);
    k_tgemm<H_DIM, 2><<<N_BLK, 256, SMEM_DYN>>>(nullptr, W2, b2, out, nullptr, nullptr, nullptr);
}

// round 12
// speedup vs baseline: 1.2073x; 1.0010x over previous
#include <cuda_runtime.h>
#include <cuda_bf16.h>
#include <cstdint>

#define N_NODES 50000
#define N_EDGES 800000
#define D_IN    256
#define H_DIM   96
#define BN_EPS  1e-5f

#define BM 128
#define N_BLK 391          // ceil(50000/128)
#define PSTRIDE 400
#define KC 32              // k-chunk (fp32 elems)
#define PA 40              // smem row pitch in bf16 elems (80B, conflict-free)
#define EPB 32             // edges per scatter block

// ---------------- device scratch ----------------
__device__ __align__(16) float g_h0[N_NODES * H_DIM];
__device__ __align__(16) float g_z [N_NODES * H_DIM];
__device__ __align__(16) float g_h [N_NODES * H_DIM];
__device__ float g_psum [H_DIM * PSTRIDE];
__device__ float g_psq  [H_DIM * PSTRIDE];
__device__ float g_scale[H_DIM];
__device__ float g_shift[H_DIM];
__device__ int   g_is64;
__device__ int   g_done = 0;

// ---------------- smem layout (bytes into dynamic smem) ----------------
#define OFF_SCALE 0
#define OFF_SHIFT 384
#define OFF_A     768
#define A_HL      10240            // 128 rows * 40 elems * 2B
#define OFF_B     (OFF_A + 4 * A_HL)
#define B_HL      7680             // 96 * 40 * 2
#define SMEM_DYN  (OFF_B + 4 * B_HL)        // 72448

#define MMA(d, a, b) \
    asm volatile("mma.sync.aligned.m16n8k16.row.col.f32.bf16.bf16.f32 " \
                 "{%0,%1,%2,%3},{%4,%5,%6,%7},{%8,%9},{%0,%1,%2,%3};" \
                 : "+f"(d[0]), "+f"(d[1]), "+f"(d[2]), "+f"(d[3]) \
                 : "r"(a[0]), "r"(a[1]), "r"(a[2]), "r"(a[3]), "r"(b[0]), "r"(b[1]))

__device__ __forceinline__ uint32_t pack_hi(float v0, float v1, float& r0, float& r1) {
    __nv_bfloat162 hp = __floats2bfloat162_rn(v0, v1);
    r0 = __bfloat162float(__low2bfloat16(hp));
    r1 = __bfloat162float(__high2bfloat16(hp));
    return *reinterpret_cast<uint32_t*>(&hp);
}

// =====================================================================
// Split-bf16 tensor-core GEMM via mma.sync:
//   out[N,96] = A[N,KD] @ W[96,KD]^T + bias
// MODE 0: A = x -> g_h0, g_z   (+ edge dtype probe in block 0)
// MODE 1: A = g_z -> g_h + BN partials; LAST block -> scale/shift
// MODE 2: A = g_h (BN+ReLU on load) -> out
// =====================================================================
template<int KD, int MODE>
__global__ __launch_bounds__(256) void k_tgemm(const float* __restrict__ A_,
                                               const float* __restrict__ W,
                                               const float* __restrict__ bias,
                                               float* __restrict__ out,
                                               const int* __restrict__ ei32,
                                               const float* __restrict__ gamma,
                                               const float* __restrict__ beta) {
    constexpr int NC = KD / KC;
    extern __shared__ char smem[];

    const int tid    = threadIdx.x;
    const int lane   = tid & 31;
    const int wid    = tid >> 5;
    const int warp_m = wid >> 1;
    const int warp_n = wid & 1;
    const int g      = lane >> 2;
    const int t4     = lane & 3;
    const int row0   = blockIdx.x * BM;

    float* s_scale = (float*)(smem + OFF_SCALE);
    float* s_shift = (float*)(smem + OFF_SHIFT);
    __shared__ int s_last;

    if (MODE == 0 && blockIdx.x == 0 && tid == 0) {
        int nz = 0;
#pragma unroll
        for (int i = 0; i < 64; i++) nz |= ei32[2 * i + 1];
        g_is64 = (nz == 0) ? 1 : 0;
        g_done = 0;
    }
    if (MODE == 2 && tid < H_DIM) {
        s_scale[tid] = g_scale[tid];
        s_shift[tid] = g_shift[tid];
    }
    __syncthreads();

    const float* Ap = (MODE == 0) ? A_ : (MODE == 1 ? g_z : g_h);

    auto pAh = [&](int b) { return (char*)smem + OFF_A + b * 2 * A_HL; };
    auto pAl = [&](int b) { return (char*)smem + OFF_A + b * 2 * A_HL + A_HL; };
    auto pBh = [&](int b) { return (char*)smem + OFF_B + b * 2 * B_HL; };
    auto pBl = [&](int b) { return (char*)smem + OFF_B + b * 2 * B_HL + B_HL; };

    const int arow  = tid >> 1;
    const int ahalf = (tid & 1) * 16;
    float ra[16];
    float rb[12];

    auto ldgA = [&](int c) {
        const int gr = row0 + arow;
        const int kb = c * KC + ahalf;
        if (gr < N_NODES) {
#pragma unroll
            for (int q = 0; q < 4; q++) {
                float4 f = *reinterpret_cast<const float4*>(&Ap[(size_t)gr * KD + kb + q * 4]);
                ra[q*4+0] = f.x; ra[q*4+1] = f.y; ra[q*4+2] = f.z; ra[q*4+3] = f.w;
            }
            if (MODE == 2) {
#pragma unroll
                for (int q = 0; q < 16; q++)
                    ra[q] = fmaxf(ra[q] * s_scale[kb + q] + s_shift[kb + q], 0.f);
            }
        } else {
#pragma unroll
            for (int q = 0; q < 16; q++) ra[q] = 0.f;
        }
    };
    auto stsA = [&](int b) {
        char* ah = pAh(b);
        char* al = pAl(b);
#pragma unroll
        for (int j = 0; j < 8; j++) {
            float v0 = ra[2*j], v1 = ra[2*j+1], h0, h1;
            uint32_t hp = pack_hi(v0, v1, h0, h1);
            __nv_bfloat162 lo2 = __floats2bfloat162_rn(v0 - h0, v1 - h1);
            int boff = (arow * PA + ahalf + 2*j) * 2;
            *reinterpret_cast<uint32_t*>(ah + boff) = hp;
            *reinterpret_cast<uint32_t*>(al + boff) = *reinterpret_cast<uint32_t*>(&lo2);
        }
    };
    auto ldgB = [&](int c) {
#pragma unroll
        for (int q = 0; q < 3; q++) {
            int f4 = tid + q * 256;
            int rw = f4 >> 3;
            int kq = (f4 & 7) * 4;
            float4 f = *reinterpret_cast<const float4*>(&W[(size_t)rw * KD + c * KC + kq]);
            rb[q*4+0] = f.x; rb[q*4+1] = f.y; rb[q*4+2] = f.z; rb[q*4+3] = f.w;
        }
    };
    auto stsB = [&](int b) {
        char* bh = pBh(b);
        char* bl = pBl(b);
#pragma unroll
        for (int q = 0; q < 3; q++) {
            int f4 = tid + q * 256;
            int rw = f4 >> 3;
            int kq = (f4 & 7) * 4;
#pragma unroll
            for (int j = 0; j < 2; j++) {
                float v0 = rb[q*4 + 2*j], v1 = rb[q*4 + 2*j + 1], h0, h1;
                uint32_t hp = pack_hi(v0, v1, h0, h1);
                __nv_bfloat162 lo2 = __floats2bfloat162_rn(v0 - h0, v1 - h1);
                int boff = (rw * PA + kq + 2*j) * 2;
                *reinterpret_cast<uint32_t*>(bh + boff) = hp;
                *reinterpret_cast<uint32_t*>(bl + boff) = *reinterpret_cast<uint32_t*>(&lo2);
            }
        }
    };

    float acc[2][6][4];
#pragma unroll
    for (int mt = 0; mt < 2; mt++)
#pragma unroll
        for (int nt = 0; nt < 6; nt++)
#pragma unroll
            for (int q = 0; q < 4; q++) acc[mt][nt][q] = 0.f;

    auto compute = [&](int b) {
        const char* Ah = pAh(b);
        const char* Al = pAl(b);
        const char* Bh = pBh(b);
        const char* Bl = pBl(b);
#pragma unroll
        for (int kk = 0; kk < KC; kk += 16) {
            uint32_t ah[2][4], al[2][4], bh[6][2], bl[6][2];
#pragma unroll
            for (int mt = 0; mt < 2; mt++) {
                int r0 = warp_m * 32 + mt * 16 + g;
                int e0 = (r0 * PA + kk + t4 * 2) * 2;
                int e1 = ((r0 + 8) * PA + kk + t4 * 2) * 2;
                ah[mt][0] = *reinterpret_cast<const uint32_t*>(Ah + e0);
                ah[mt][1] = *reinterpret_cast<const uint32_t*>(Ah + e1);
                ah[mt][2] = *reinterpret_cast<const uint32_t*>(Ah + e0 + 16);
                ah[mt][3] = *reinterpret_cast<const uint32_t*>(Ah + e1 + 16);
                al[mt][0] = *reinterpret_cast<const uint32_t*>(Al + e0);
                al[mt][1] = *reinterpret_cast<const uint32_t*>(Al + e1);
                al[mt][2] = *reinterpret_cast<const uint32_t*>(Al + e0 + 16);
                al[mt][3] = *reinterpret_cast<const uint32_t*>(Al + e1 + 16);
            }
#pragma unroll
            for (int nt = 0; nt < 6; nt++) {
                int n = warp_n * 48 + nt * 8 + g;
                int e = (n * PA + kk + t4 * 2) * 2;
                bh[nt][0] = *reinterpret_cast<const uint32_t*>(Bh + e);
                bh[nt][1] = *reinterpret_cast<const uint32_t*>(Bh + e + 16);
                bl[nt][0] = *reinterpret_cast<const uint32_t*>(Bl + e);
                bl[nt][1] = *reinterpret_cast<const uint32_t*>(Bl + e + 16);
            }
#pragma unroll
            for (int mt = 0; mt < 2; mt++)
#pragma unroll
                for (int nt = 0; nt < 6; nt++) {
                    MMA(acc[mt][nt], ah[mt], bh[nt]);
                    MMA(acc[mt][nt], al[mt], bh[nt]);
                    MMA(acc[mt][nt], ah[mt], bl[nt]);
                }
        }
    };

    ldgA(0); ldgB(0);
    stsA(0); stsB(0);
    __syncthreads();
    for (int c = 0; c < NC; c++) {
        const bool pf = (c + 1 < NC);
        if (pf) { ldgA(c + 1); ldgB(c + 1); }
        compute(c & 1);
        if (pf) {
            stsA((c + 1) & 1); stsB((c + 1) & 1);
            __syncthreads();
        }
    }
    __syncthreads();

    // ---- epilogue: acc -> smem staging (pitch 100 floats) ----
    float* sD = (float*)(smem + OFF_A);
#pragma unroll
    for (int mt = 0; mt < 2; mt++) {
        int r0 = warp_m * 32 + mt * 16 + g;
#pragma unroll
        for (int nt = 0; nt < 6; nt++) {
            int cb = warp_n * 48 + nt * 8 + t4 * 2;
            sD[r0 * 100 + cb]       = acc[mt][nt][0];
            sD[r0 * 100 + cb + 1]   = acc[mt][nt][1];
            sD[(r0+8) * 100 + cb]   = acc[mt][nt][2];
            sD[(r0+8) * 100 + cb+1] = acc[mt][nt][3];
        }
    }
    __syncthreads();

    const int rmax = min(BM, N_NODES - row0);

    if (MODE == 1) {
        // BN partials: 192 threads, 2 row-halves per column
        __shared__ float s2sum[2][H_DIM], s2sq[2][H_DIM];
        if (tid < 2 * H_DIM) {
            const int c    = tid % H_DIM;
            const int half = tid / H_DIM;
            const float b  = bias[c];
            const int rlo  = half * 64;
            const int rhi  = min(rmax, rlo + 64);
            float s = 0.f, q = 0.f;
            for (int r = rlo; r < rhi; r++) {
                float v = sD[r * 100 + c] + b;
                s += v; q += v * v;
            }
            s2sum[half][c] = s; s2sq[half][c] = q;
        }
        __syncthreads();
        if (tid < H_DIM) {
            g_psum[tid * PSTRIDE + blockIdx.x] = s2sum[0][tid] + s2sum[1][tid];
            g_psq [tid * PSTRIDE + blockIdx.x] = s2sq [0][tid] + s2sq [1][tid];
        }
    }

    for (int idx = tid; idx < rmax * 24; idx += 256) {
        int r = idx / 24, c4 = idx % 24;
        float4 v = *reinterpret_cast<const float4*>(&sD[r * 100 + c4 * 4]);
        float4 b = *reinterpret_cast<const float4*>(&bias[c4 * 4]);
        v.x += b.x; v.y += b.y; v.z += b.z; v.w += b.w;
        size_t o = (size_t)(row0 + r) * H_DIM + c4 * 4;
        if (MODE == 0) {
            *reinterpret_cast<float4*>(&g_h0[o]) = v;
            *reinterpret_cast<float4*>(&g_z [o]) = v;
        } else if (MODE == 1) {
            *reinterpret_cast<float4*>(&g_h[o]) = v;
        } else {
            *reinterpret_cast<float4*>(&out[o]) = v;
        }
    }

    if (MODE == 1) {
        // last finishing block reduces partials -> scale/shift
        __threadfence();
        __syncthreads();
        if (tid == 0) s_last = (atomicAdd(&g_done, 1) == N_BLK - 1) ? 1 : 0;
        __syncthreads();
        if (s_last) {
            if (tid < H_DIM) {
                float s = 0.f, q = 0.f;
                for (int b = 0; b < N_BLK; b++) {
                    s += g_psum[tid * PSTRIDE + b];
                    q += g_psq [tid * PSTRIDE + b];
                }
                const float inv_n = 1.0f / (float)N_NODES;
                float mu  = s * inv_n;
                float var = q * inv_n - mu * mu;
                float sc  = gamma[tid] * rsqrtf(var + BN_EPS);
                g_scale[tid] = sc;
                g_shift[tid] = beta[tid] - mu * sc;
            }
            if (tid == 0) g_done = 0;
        }
    }
}

// =====================================================================
// Scatter-add  z[dst] += h0[src].  Block = 32 edges; indices staged in
// smem once; each thread: 3 col-groups (float4) of its edge.
// =====================================================================
__global__ __launch_bounds__(256) void k_scatter(const void* __restrict__ ei) {
    __shared__ int s_src[EPB], s_dst[EPB];
    const int tid = threadIdx.x;
    const int e0  = blockIdx.x * EPB;

    if (tid < 2 * EPB) {
        const int which = tid >> 5;          // 0: src, 1: dst
        const int i     = tid & 31;
        const int e     = e0 + i;
        int v = -1;
        if (e < N_EDGES) {
            const size_t off = which ? (size_t)N_EDGES + e : (size_t)e;
            v = g_is64 ? (int)((const long long*)ei)[off]
                       : ((const int*)ei)[off];
        }
        if (which) s_dst[i] = v; else s_src[i] = v;
    }
    __syncthreads();

    const int eL = tid >> 3;                 // 0..31
    const int c8 = tid & 7;                  // 0..7
    if (e0 + eL >= N_EDGES) return;
    const int src = s_src[eL];
    const int dst = s_dst[eL];
    if ((unsigned)src >= N_NODES || (unsigned)dst >= N_NODES) return;

    const float* srow = &g_h0[(size_t)src * H_DIM];
    float*       drow = &g_z [(size_t)dst * H_DIM];
#pragma unroll
    for (int j = 0; j < 3; j++) {
        const int c = (c8 + j * 8) * 4;
        const float4 v = *reinterpret_cast<const float4*>(srow + c);
        asm volatile("red.global.add.v4.f32 [%0], {%1,%2,%3,%4};"
                     :: "l"(drow + c), "f"(v.x), "f"(v.y), "f"(v.z), "f"(v.w)
                     : "memory");
    }
}

// =====================================================================
// launch
// =====================================================================
extern "C" void kernel_launch(void* const* d_in, const int* in_sizes, int n_in,
                              void* d_out, int out_size) {
    const float* x     = (const float*)d_in[0];
    const void*  ei    = d_in[1];
    const float* W0    = (const float*)d_in[2];
    const float* b0    = (const float*)d_in[3];
    const float* W1    = (const float*)d_in[4];
    const float* b1    = (const float*)d_in[5];
    const float* gamma = (const float*)d_in[6];
    const float* beta  = (const float*)d_in[7];
    const float* W2    = (const float*)d_in[8];
    const float* b2    = (const float*)d_in[9];
    float*       out   = (float*)d_out;

    static bool attr_done = false;
    if (!attr_done) {
        cudaFuncSetAttribute(k_tgemm<D_IN, 0>, cudaFuncAttributeMaxDynamicSharedMemorySize, SMEM_DYN);
        cudaFuncSetAttribute(k_tgemm<H_DIM, 1>, cudaFuncAttributeMaxDynamicSharedMemorySize, SMEM_DYN);
        cudaFuncSetAttribute(k_tgemm<H_DIM, 2>, cudaFuncAttributeMaxDynamicSharedMemorySize, SMEM_DYN);
        attr_done = true;
    }

    const int scat_blocks = (N_EDGES + EPB - 1) / EPB;   // 25000

    k_tgemm<D_IN, 0><<<N_BLK, 256, SMEM_DYN>>>(x, W0, b0, nullptr, (const int*)ei, nullptr, nullptr);
    k_scatter<<<scat_blocks, 256>>>(ei);
    k_tgemm<H_DIM, 1><<<N_BLK, 256, SMEM_DYN>>>(nullptr, W1, b1, nullptr, nullptr, gamma, beta);
    k_tgemm<H_DIM, 2><<<N_BLK, 256, SMEM_DYN>>>(nullptr, W2, b2, out, nullptr, nullptr, nullptr);
}